// round 7
// baseline (speedup 1.0000x reference)
#include <cuda_runtime.h>
#include <cstdint>

typedef unsigned long long ull;
#define FULLMASK 0xFFFFFFFFu

// Scratch for combined features [vx,vy,vz, rx,ry,rz] per row (64*1024 rows).
__device__ float g_comb[64 * 1024 * 6];

// ---------------------------------------------------------------------------
// Kernel 1: top-4 smallest distances per row -> combined features
// One warp per row. Keys are ((u32)float_bits << 32) | index, so a single
// u64 '<' gives exact (value asc, index asc) ordering == JAX top_k ties.
// ---------------------------------------------------------------------------

__device__ __forceinline__ void cswap_u64(ull &a, ull &b) {
    if (b < a) { ull t = a; a = b; b = t; }
}

__device__ __forceinline__ void ins4(ull k, ull &k0, ull &k1, ull &k2, ull &k3) {
    if (k < k3) {
        k3 = k;
        cswap_u64(k2, k3);
        cswap_u64(k1, k2);
        cswap_u64(k0, k1);
    }
}

__global__ void __launch_bounds__(256) topk_kernel(const float* __restrict__ dm,
                                                   const float* __restrict__ vel) {
    const int warp = threadIdx.x >> 5;
    const int lane = threadIdx.x & 31;
    const int row  = blockIdx.x * 8 + warp;   // < 65536
    const float* drow = dm + (size_t)row * 1024;

    ull k0 = ~0ull, k1 = ~0ull, k2 = ~0ull, k3 = ~0ull;

    #pragma unroll 4
    for (int j = lane; j < 1024; j += 32) {
        float d = drow[j];
        ull key = ((ull)__float_as_uint(d) << 32) | (unsigned)j;
        ins4(key, k0, k1, k2, k3);
    }

    // Warp butterfly merge of per-lane sorted top-4 lists.
    #pragma unroll
    for (int off = 16; off; off >>= 1) {
        ull m0 = __shfl_xor_sync(FULLMASK, k0, off);
        ull m1 = __shfl_xor_sync(FULLMASK, k1, off);
        ull m2 = __shfl_xor_sync(FULLMASK, k2, off);
        ull m3 = __shfl_xor_sync(FULLMASK, k3, off);
        ins4(m0, k0, k1, k2, k3);
        ins4(m1, k0, k1, k2, k3);
        ins4(m2, k0, k1, k2, k3);
        ins4(m3, k0, k1, k2, k3);
    }

    if (lane == 0) {
        const int b = row >> 10;
        const int a = row & 1023;
        const float* vb = vel + (size_t)b * (1024 * 3);
        // ranks 1,2,3 (rank 0 dropped per idx[...,1:])
        const int i1 = (int)(unsigned)k1;
        const int i2 = (int)(unsigned)k2;
        const int i3 = (int)(unsigned)k3;
        float sx = vb[a * 3 + 0], sy = vb[a * 3 + 1], sz = vb[a * 3 + 2];
        float nx = vb[i1 * 3 + 0] + vb[i2 * 3 + 0] + vb[i3 * 3 + 0];
        float ny = vb[i1 * 3 + 1] + vb[i2 * 3 + 1] + vb[i3 * 3 + 1];
        float nz = vb[i1 * 3 + 2] + vb[i2 * 3 + 2] + vb[i3 * 3 + 2];
        const float third = 1.0f / 3.0f;
        float* c = g_comb + (size_t)row * 6;
        c[0] = sx; c[1] = sy; c[2] = sz;
        c[3] = sx - nx * third;
        c[4] = sy - ny * third;
        c[5] = sz - nz * third;
    }
}

// ---------------------------------------------------------------------------
// Kernel 2: fused MLP: h = relu(c @ W1 + b1); h = LN(h)*g+b; out = h @ W2 + b2
// 64 rows per block, 256 threads. Full-fp32 GEMM via packed fma.rn.f32x2
// (2x FFMA throughput, no precision loss). h kept transposed in smem
// (stride 72 -> conflict-free), W2 double-buffered from L2.
// ---------------------------------------------------------------------------

#define MT 64
#define KC 8
#define HS_STRIDE 72
#define HS_F   (256 * HS_STRIDE)   // 18432 floats
#define W2B_F  (2 * KC * 256)      //  4096 floats
#define W1_F   (6 * 256)           //  1536 floats
#define SMEM_FLOATS (HS_F + W2B_F + W1_F + 3 * 256 + MT * 6)
#define SMEM_BYTES  (SMEM_FLOATS * 4)

__device__ __forceinline__ ull pk2(float lo, float hi) {
    ull r;
    asm("mov.b64 %0, {%1, %2};" : "=l"(r) : "f"(lo), "f"(hi));
    return r;
}
__device__ __forceinline__ void upk2(ull v, float &lo, float &hi) {
    asm("mov.b64 {%0, %1}, %2;" : "=f"(lo), "=f"(hi) : "l"(v));
}
__device__ __forceinline__ void ffma2(ull &d, ull a, ull b) {
    asm("fma.rn.f32x2 %0, %1, %2, %0;" : "+l"(d) : "l"(a), "l"(b));
}

__global__ void __launch_bounds__(256, 2) mlp_kernel(
    const float* __restrict__ W1, const float* __restrict__ b1,
    const float* __restrict__ gamma, const float* __restrict__ beta,
    const float* __restrict__ W2, const float* __restrict__ b2,
    float* __restrict__ out)
{
    extern __shared__ float sm[];
    float* hs  = sm;               // [256][HS_STRIDE], h transposed: hs[e][row]
    float* w2b = hs + HS_F;        // double buffer: 2 x [KC][256]
    float* w1s = w2b + W2B_F;      // [6][256]
    float* b1s = w1s + W1_F;
    float* gs  = b1s + 256;
    float* bs  = gs + 256;
    float* cmb = bs + 256;         // [MT][6]

    const int t = threadIdx.x;
    const int row0 = blockIdx.x * MT;

    for (int i = t; i < MT * 6; i += 256) cmb[i] = g_comb[(size_t)row0 * 6 + i];
    for (int i = t; i < W1_F; i += 256)   w1s[i] = W1[i];
    b1s[t] = b1[t]; gs[t] = gamma[t]; bs[t] = beta[t];
    __syncthreads();

    // ---- Phase A: h = relu(c @ W1 + b1), then LayerNorm, into transposed smem
    {
        const int r = t >> 2;      // row 0..63
        const int q = t & 3;       // col quadrant
        float c0 = cmb[r*6+0], c1 = cmb[r*6+1], c2 = cmb[r*6+2];
        float c3 = cmb[r*6+3], c4 = cmb[r*6+4], c5 = cmb[r*6+5];
        float sum = 0.f, sq = 0.f;
        #pragma unroll 8
        for (int jj = 0; jj < 64; jj++) {
            int e = q + 4 * jj;
            float x = b1s[e];
            x = fmaf(c0, w1s[e],        x);
            x = fmaf(c1, w1s[256 + e],  x);
            x = fmaf(c2, w1s[512 + e],  x);
            x = fmaf(c3, w1s[768 + e],  x);
            x = fmaf(c4, w1s[1024 + e], x);
            x = fmaf(c5, w1s[1280 + e], x);
            x = fmaxf(x, 0.f);
            hs[e * HS_STRIDE + r] = x;
            sum += x;
            sq = fmaf(x, x, sq);
        }
        sum += __shfl_xor_sync(FULLMASK, sum, 1);
        sq  += __shfl_xor_sync(FULLMASK, sq, 1);
        sum += __shfl_xor_sync(FULLMASK, sum, 2);
        sq  += __shfl_xor_sync(FULLMASK, sq, 2);
        float mu   = sum * (1.f / 256.f);
        float var  = sq * (1.f / 256.f) - mu * mu;
        float rstd = rsqrtf(var + 1e-5f);
        #pragma unroll 8
        for (int jj = 0; jj < 64; jj++) {
            int e = q + 4 * jj;
            float x = hs[e * HS_STRIDE + r];
            hs[e * HS_STRIDE + r] = (x - mu) * rstd * gs[e] + bs[e];
        }
    }
    __syncthreads();

    // ---- Phase B: out = h @ W2 + b2, 8x8 per thread with f32x2 pairs on rows
    const int lane = t & 31;
    const int wrp  = t >> 5;
    const int r0   = wrp * 8;

    ull acc[4][8];
    #pragma unroll
    for (int p = 0; p < 4; p++)
        #pragma unroll
        for (int j = 0; j < 8; j++) acc[p][j] = 0ull;

    const float4* wsrc = (const float4*)W2;
    // preload chunk 0
    {
        float4 f0 = wsrc[t];
        float4 f1 = wsrc[t + 256];
        float4* dst = (float4*)w2b;
        dst[t] = f0; dst[t + 256] = f1;
    }
    __syncthreads();

    #pragma unroll 1
    for (int c = 0; c < 32; c++) {
        float4 f0, f1;
        if (c < 31) {
            f0 = wsrc[(c + 1) * 512 + t];
            f1 = wsrc[(c + 1) * 512 + t + 256];
        }
        const float* wcur = w2b + (c & 1) * (KC * 256);
        #pragma unroll
        for (int kk = 0; kk < KC; kk++) {
            int k = c * KC + kk;
            const float* hp = hs + k * HS_STRIDE + r0;
            float4 ha = *(const float4*)hp;
            float4 hb = *(const float4*)(hp + 4);
            ull a0 = pk2(ha.x, ha.y);
            ull a1 = pk2(ha.z, ha.w);
            ull a2 = pk2(hb.x, hb.y);
            ull a3 = pk2(hb.z, hb.w);
            const float* wr = wcur + kk * 256 + lane;
            #pragma unroll
            for (int j = 0; j < 8; j++) {
                float w = wr[32 * j];
                ull wd = pk2(w, w);
                ffma2(acc[0][j], a0, wd);
                ffma2(acc[1][j], a1, wd);
                ffma2(acc[2][j], a2, wd);
                ffma2(acc[3][j], a3, wd);
            }
        }
        if (c < 31) {
            float4* dst = (float4*)(w2b + ((c + 1) & 1) * (KC * 256));
            dst[t] = f0; dst[t + 256] = f1;
        }
        __syncthreads();
    }

    // ---- Epilogue
    float bb[8];
    #pragma unroll
    for (int j = 0; j < 8; j++) bb[j] = b2[lane + 32 * j];
    #pragma unroll
    for (int p = 0; p < 4; p++) {
        float* o0 = out + (size_t)(row0 + r0 + 2 * p) * 256;
        float* o1 = o0 + 256;
        #pragma unroll
        for (int j = 0; j < 8; j++) {
            float lo, hi;
            upk2(acc[p][j], lo, hi);
            o0[lane + 32 * j] = lo + bb[j];
            o1[lane + 32 * j] = hi + bb[j];
        }
    }
}

// ---------------------------------------------------------------------------

extern "C" void kernel_launch(void* const* d_in, const int* in_sizes, int n_in,
                              void* d_out, int out_size) {
    const float* vel   = (const float*)d_in[0];
    const float* dm    = (const float*)d_in[1];
    const float* W1    = (const float*)d_in[2];
    const float* b1    = (const float*)d_in[3];
    const float* gamma = (const float*)d_in[4];
    const float* beta  = (const float*)d_in[5];
    const float* W2    = (const float*)d_in[6];
    const float* b2    = (const float*)d_in[7];
    float* out = (float*)d_out;

    topk_kernel<<<8192, 256>>>(dm, vel);

    cudaFuncSetAttribute(mlp_kernel, cudaFuncAttributeMaxDynamicSharedMemorySize,
                         SMEM_BYTES);
    mlp_kernel<<<1024, 256, SMEM_BYTES>>>(W1, b1, gamma, beta, W2, b2, out);
}

// round 8
// speedup vs baseline: 1.0557x; 1.0557x over previous
#include <cuda_runtime.h>
#include <cstdint>

typedef unsigned long long ull;
#define FULLMASK 0xFFFFFFFFu

// Scratch for combined features [vx,vy,vz, rx,ry,rz] per row (64*1024 rows).
__device__ float g_comb[64 * 1024 * 6];

// ---------------------------------------------------------------------------
// Kernel 1: top-4 smallest distances per row -> combined features.
// One LANE per row (warp = 32 rows). Tiles of 32 rows x 128 cols are staged
// through swizzled shared memory so DRAM traffic stays fully coalesced while
// each lane scans its own complete row. A cheap fp32 "min-of-4 <= 4th-best"
// prefilter guards the exact u64 insertion, so the expensive path runs only
// ~26 times per 1024 elements instead of every element.
// Keys are ((u32)float_bits << 32) | index: one u64 '<' gives exact
// (value asc, index asc) ordering == JAX top_k tie-breaking.
// ---------------------------------------------------------------------------

__device__ __forceinline__ void cswap_u64(ull &a, ull &b) {
    if (b < a) { ull t = a; a = b; b = t; }
}

#define TK_WARPS 2

__global__ void __launch_bounds__(TK_WARPS * 32) topk_kernel(
    const float* __restrict__ dm, const float* __restrict__ vel)
{
    __shared__ float4 tile[TK_WARPS][32][32];   // 16KB per warp, swizzled

    const int warp = threadIdx.x >> 5;
    const int lane = threadIdx.x & 31;
    const int row0 = (blockIdx.x * TK_WARPS + warp) * 32;
    const int myrow = row0 + lane;
    const float* base = dm + (size_t)row0 * 1024;

    const ull INIT = ((ull)0x7F800000u << 32) | 0xFFFFFFFFull;  // (+inf, maxidx)
    ull k0 = INIT, k1 = INIT, k2 = INIT, k3 = INIT;
    float t3f = __int_as_float(0x7F800000);     // +inf

    #pragma unroll 1
    for (int t = 0; t < 8; t++) {
        // ---- stage tile: 32 rows x 128 cols, coalesced LDG.128 per row.
        // swizzle: logical (row r, 16B-chunk c) -> physical chunk c ^ r.
        #pragma unroll
        for (int r = 0; r < 32; r++) {
            float4 v = *(const float4*)(base + (size_t)r * 1024 + t * 128 + lane * 4);
            tile[warp][r][lane ^ r] = v;
        }
        __syncwarp();

        // ---- each lane scans its own row (r = lane) within the tile
        #pragma unroll 4
        for (int g = 0; g < 32; g++) {
            float4 v = tile[warp][lane][g ^ lane];
            float mn = fminf(fminf(v.x, v.y), fminf(v.z, v.w));
            if (mn <= t3f) {
                const int jb = t * 128 + g * 4;
                float e[4] = {v.x, v.y, v.z, v.w};
                #pragma unroll
                for (int c = 0; c < 4; c++) {
                    if (e[c] <= t3f) {
                        ull key = ((ull)__float_as_uint(e[c]) << 32) | (unsigned)(jb + c);
                        if (key < k3) {
                            k3 = key;
                            cswap_u64(k2, k3);
                            cswap_u64(k1, k2);
                            cswap_u64(k0, k1);
                            t3f = __uint_as_float((unsigned)(k3 >> 32));
                        }
                    }
                }
            }
        }
        __syncwarp();
    }

    // ---- writeout: every lane owns a full row's final top-4
    {
        const int b = myrow >> 10;
        const int a = myrow & 1023;
        const float* vb = vel + (size_t)b * (1024 * 3);
        // ranks 1,2,3 (rank 0 dropped per idx[...,1:])
        const int i1 = (int)(unsigned)k1;
        const int i2 = (int)(unsigned)k2;
        const int i3 = (int)(unsigned)k3;
        float sx = vb[a * 3 + 0], sy = vb[a * 3 + 1], sz = vb[a * 3 + 2];
        float nx = vb[i1 * 3 + 0] + vb[i2 * 3 + 0] + vb[i3 * 3 + 0];
        float ny = vb[i1 * 3 + 1] + vb[i2 * 3 + 1] + vb[i3 * 3 + 1];
        float nz = vb[i1 * 3 + 2] + vb[i2 * 3 + 2] + vb[i3 * 3 + 2];
        const float third = 1.0f / 3.0f;
        float* c = g_comb + (size_t)myrow * 6;
        c[0] = sx; c[1] = sy; c[2] = sz;
        c[3] = sx - nx * third;
        c[4] = sy - ny * third;
        c[5] = sz - nz * third;
    }
}

// ---------------------------------------------------------------------------
// Kernel 2: fused MLP: h = relu(c @ W1 + b1); h = LN(h)*g+b; out = h @ W2 + b2
// 64 rows per block, 256 threads. Full-fp32 GEMM via packed fma.rn.f32x2
// (2x FFMA throughput, no precision loss). h kept transposed in smem
// (stride 72 -> bank-conflict-free), W2 double-buffered from L2.
// (unchanged from R6 — fma pipe already at 57% = within 1.7x of f32x2 floor)
// ---------------------------------------------------------------------------

#define MT 64
#define KC 8
#define HS_STRIDE 72
#define HS_F   (256 * HS_STRIDE)   // 18432 floats
#define W2B_F  (2 * KC * 256)      //  4096 floats
#define W1_F   (6 * 256)           //  1536 floats
#define SMEM_FLOATS (HS_F + W2B_F + W1_F + 3 * 256 + MT * 6)
#define SMEM_BYTES  (SMEM_FLOATS * 4)

__device__ __forceinline__ ull pk2(float lo, float hi) {
    ull r;
    asm("mov.b64 %0, {%1, %2};" : "=l"(r) : "f"(lo), "f"(hi));
    return r;
}
__device__ __forceinline__ void upk2(ull v, float &lo, float &hi) {
    asm("mov.b64 {%0, %1}, %2;" : "=f"(lo), "=f"(hi) : "l"(v));
}
__device__ __forceinline__ void ffma2(ull &d, ull a, ull b) {
    asm("fma.rn.f32x2 %0, %1, %2, %0;" : "+l"(d) : "l"(a), "l"(b));
}

__global__ void __launch_bounds__(256, 2) mlp_kernel(
    const float* __restrict__ W1, const float* __restrict__ b1,
    const float* __restrict__ gamma, const float* __restrict__ beta,
    const float* __restrict__ W2, const float* __restrict__ b2,
    float* __restrict__ out)
{
    extern __shared__ float sm[];
    float* hs  = sm;               // [256][HS_STRIDE], h transposed: hs[e][row]
    float* w2b = hs + HS_F;        // double buffer: 2 x [KC][256]
    float* w1s = w2b + W2B_F;      // [6][256]
    float* b1s = w1s + W1_F;
    float* gs  = b1s + 256;
    float* bs  = gs + 256;
    float* cmb = bs + 256;         // [MT][6]

    const int t = threadIdx.x;
    const int row0 = blockIdx.x * MT;

    for (int i = t; i < MT * 6; i += 256) cmb[i] = g_comb[(size_t)row0 * 6 + i];
    for (int i = t; i < W1_F; i += 256)   w1s[i] = W1[i];
    b1s[t] = b1[t]; gs[t] = gamma[t]; bs[t] = beta[t];
    __syncthreads();

    // ---- Phase A: h = relu(c @ W1 + b1), then LayerNorm, into transposed smem
    {
        const int r = t >> 2;      // row 0..63
        const int q = t & 3;       // col quadrant
        float c0 = cmb[r*6+0], c1 = cmb[r*6+1], c2 = cmb[r*6+2];
        float c3 = cmb[r*6+3], c4 = cmb[r*6+4], c5 = cmb[r*6+5];
        float sum = 0.f, sq = 0.f;
        #pragma unroll 8
        for (int jj = 0; jj < 64; jj++) {
            int e = q + 4 * jj;
            float x = b1s[e];
            x = fmaf(c0, w1s[e],        x);
            x = fmaf(c1, w1s[256 + e],  x);
            x = fmaf(c2, w1s[512 + e],  x);
            x = fmaf(c3, w1s[768 + e],  x);
            x = fmaf(c4, w1s[1024 + e], x);
            x = fmaf(c5, w1s[1280 + e], x);
            x = fmaxf(x, 0.f);
            hs[e * HS_STRIDE + r] = x;
            sum += x;
            sq = fmaf(x, x, sq);
        }
        sum += __shfl_xor_sync(FULLMASK, sum, 1);
        sq  += __shfl_xor_sync(FULLMASK, sq, 1);
        sum += __shfl_xor_sync(FULLMASK, sum, 2);
        sq  += __shfl_xor_sync(FULLMASK, sq, 2);
        float mu   = sum * (1.f / 256.f);
        float var  = sq * (1.f / 256.f) - mu * mu;
        float rstd = rsqrtf(var + 1e-5f);
        #pragma unroll 8
        for (int jj = 0; jj < 64; jj++) {
            int e = q + 4 * jj;
            float x = hs[e * HS_STRIDE + r];
            hs[e * HS_STRIDE + r] = (x - mu) * rstd * gs[e] + bs[e];
        }
    }
    __syncthreads();

    // ---- Phase B: out = h @ W2 + b2, 8x8 per thread with f32x2 pairs on rows
    const int lane = t & 31;
    const int wrp  = t >> 5;
    const int r0   = wrp * 8;

    ull acc[4][8];
    #pragma unroll
    for (int p = 0; p < 4; p++)
        #pragma unroll
        for (int j = 0; j < 8; j++) acc[p][j] = 0ull;

    const float4* wsrc = (const float4*)W2;
    // preload chunk 0
    {
        float4 f0 = wsrc[t];
        float4 f1 = wsrc[t + 256];
        float4* dst = (float4*)w2b;
        dst[t] = f0; dst[t + 256] = f1;
    }
    __syncthreads();

    #pragma unroll 1
    for (int c = 0; c < 32; c++) {
        float4 f0, f1;
        if (c < 31) {
            f0 = wsrc[(c + 1) * 512 + t];
            f1 = wsrc[(c + 1) * 512 + t + 256];
        }
        const float* wcur = w2b + (c & 1) * (KC * 256);
        #pragma unroll
        for (int kk = 0; kk < KC; kk++) {
            int k = c * KC + kk;
            const float* hp = hs + k * HS_STRIDE + r0;
            float4 ha = *(const float4*)hp;
            float4 hb = *(const float4*)(hp + 4);
            ull a0 = pk2(ha.x, ha.y);
            ull a1 = pk2(ha.z, ha.w);
            ull a2 = pk2(hb.x, hb.y);
            ull a3 = pk2(hb.z, hb.w);
            const float* wr = wcur + kk * 256 + lane;
            #pragma unroll
            for (int j = 0; j < 8; j++) {
                float w = wr[32 * j];
                ull wd = pk2(w, w);
                ffma2(acc[0][j], a0, wd);
                ffma2(acc[1][j], a1, wd);
                ffma2(acc[2][j], a2, wd);
                ffma2(acc[3][j], a3, wd);
            }
        }
        if (c < 31) {
            float4* dst = (float4*)(w2b + ((c + 1) & 1) * (KC * 256));
            dst[t] = f0; dst[t + 256] = f1;
        }
        __syncthreads();
    }

    // ---- Epilogue
    float bb[8];
    #pragma unroll
    for (int j = 0; j < 8; j++) bb[j] = b2[lane + 32 * j];
    #pragma unroll
    for (int p = 0; p < 4; p++) {
        float* o0 = out + (size_t)(row0 + r0 + 2 * p) * 256;
        float* o1 = o0 + 256;
        #pragma unroll
        for (int j = 0; j < 8; j++) {
            float lo, hi;
            upk2(acc[p][j], lo, hi);
            o0[lane + 32 * j] = lo + bb[j];
            o1[lane + 32 * j] = hi + bb[j];
        }
    }
}

// ---------------------------------------------------------------------------

extern "C" void kernel_launch(void* const* d_in, const int* in_sizes, int n_in,
                              void* d_out, int out_size) {
    const float* vel   = (const float*)d_in[0];
    const float* dm    = (const float*)d_in[1];
    const float* W1    = (const float*)d_in[2];
    const float* b1    = (const float*)d_in[3];
    const float* gamma = (const float*)d_in[4];
    const float* beta  = (const float*)d_in[5];
    const float* W2    = (const float*)d_in[6];
    const float* b2    = (const float*)d_in[7];
    float* out = (float*)d_out;

    // 65536 rows / 32 rows-per-warp / TK_WARPS warps-per-block
    topk_kernel<<<65536 / (32 * TK_WARPS), TK_WARPS * 32>>>(dm, vel);

    cudaFuncSetAttribute(mlp_kernel, cudaFuncAttributeMaxDynamicSharedMemorySize,
                         SMEM_BYTES);
    mlp_kernel<<<1024, 256, SMEM_BYTES>>>(W1, b1, gamma, beta, W2, b2, out);
}

// round 10
// speedup vs baseline: 1.2685x; 1.2016x over previous
#include <cuda_runtime.h>
#include <cuda_fp16.h>
#include <cstdint>

typedef unsigned long long ull;
#define FULLMASK 0xFFFFFFFFu

// Scratch for combined features [vx,vy,vz, rx,ry,rz] per row (64*1024 rows).
__device__ float g_comb[64 * 1024 * 6];

// Prepped W2 (B = W2[k][n]) as mma.sync m16n8k16 B-fragment images, fp16 hi/lo.
// Layout: [nh(2)][kchunk(4)] blocks of 16KB; within block:
// ((kkc*16 + nfh)*32 + lane) * 8 bytes = {b0,b1} u32 pair.
__device__ __align__(16) unsigned char g_bhi[2 * 4 * 16384];
__device__ __align__(16) unsigned char g_blo[2 * 4 * 16384];

// ---------------------------------------------------------------------------
// Kernel 0: prep W2 -> fp16 hi/lo B-fragment images (runs once per launch).
// ---------------------------------------------------------------------------
__device__ __forceinline__ uint32_t pkh2(float lo, float hi) {
    uint32_t r;
    asm("cvt.rn.f16x2.f32 %0, %1, %2;" : "=r"(r) : "f"(hi), "f"(lo));
    return r;
}
__device__ __forceinline__ void splitf(float x, float &hi, float &lo) {
    __half h = __float2half_rn(x);
    hi = __half2float(h);
    lo = x - hi;
}

__global__ void __launch_bounds__(256) w2prep_kernel(const float* __restrict__ W2) {
    const int gid = blockIdx.x * 256 + threadIdx.x;   // 0..16383
    const int lane = gid & 31;
    const int nf = (gid >> 5) & 31;
    const int kk = gid >> 10;                          // 0..15
    const int k0 = kk * 16 + (lane & 3) * 2;
    const int n  = nf * 8 + (lane >> 2);
    float w00 = W2[(k0 + 0) * 256 + n];
    float w01 = W2[(k0 + 1) * 256 + n];
    float w10 = W2[(k0 + 8) * 256 + n];
    float w11 = W2[(k0 + 9) * 256 + n];
    float h00, l00, h01, l01, h10, l10, h11, l11;
    splitf(w00, h00, l00); splitf(w01, h01, l01);
    splitf(w10, h10, l10); splitf(w11, h11, l11);
    const int nh = nf >> 4, c = kk >> 2, kkc = kk & 3, nfh = nf & 15;
    const size_t off = (size_t)(nh * 4 + c) * 16384
                     + (size_t)(((kkc * 16 + nfh) * 32 + lane) * 8);
    *(uint2*)(g_bhi + off) = make_uint2(pkh2(h00, h01), pkh2(h10, h11));
    *(uint2*)(g_blo + off) = make_uint2(pkh2(l00, l01), pkh2(l10, l11));
}

// ---------------------------------------------------------------------------
// Kernel 1: top-4 smallest distances per row -> combined features.
// (unchanged — pinned near the distance-matrix stream ceiling)
// ---------------------------------------------------------------------------

__device__ __forceinline__ void cswap_u64(ull &a, ull &b) {
    if (b < a) { ull t = a; a = b; b = t; }
}

#define TK_WARPS 2

__global__ void __launch_bounds__(TK_WARPS * 32) topk_kernel(
    const float* __restrict__ dm, const float* __restrict__ vel)
{
    __shared__ float4 tile[TK_WARPS][32][32];

    const int warp = threadIdx.x >> 5;
    const int lane = threadIdx.x & 31;
    const int row0 = (blockIdx.x * TK_WARPS + warp) * 32;
    const int myrow = row0 + lane;
    const float* base = dm + (size_t)row0 * 1024;

    const ull INIT = ((ull)0x7F800000u << 32) | 0xFFFFFFFFull;
    ull k0 = INIT, k1 = INIT, k2 = INIT, k3 = INIT;
    float t3f = __int_as_float(0x7F800000);

    #pragma unroll 1
    for (int t = 0; t < 8; t++) {
        #pragma unroll
        for (int r = 0; r < 32; r++) {
            float4 v = *(const float4*)(base + (size_t)r * 1024 + t * 128 + lane * 4);
            tile[warp][r][lane ^ r] = v;
        }
        __syncwarp();

        #pragma unroll 4
        for (int g = 0; g < 32; g++) {
            float4 v = tile[warp][lane][g ^ lane];
            float mn = fminf(fminf(v.x, v.y), fminf(v.z, v.w));
            if (mn <= t3f) {
                const int jb = t * 128 + g * 4;
                float e[4] = {v.x, v.y, v.z, v.w};
                #pragma unroll
                for (int c = 0; c < 4; c++) {
                    if (e[c] <= t3f) {
                        ull key = ((ull)__float_as_uint(e[c]) << 32) | (unsigned)(jb + c);
                        if (key < k3) {
                            k3 = key;
                            cswap_u64(k2, k3);
                            cswap_u64(k1, k2);
                            cswap_u64(k0, k1);
                            t3f = __uint_as_float((unsigned)(k3 >> 32));
                        }
                    }
                }
            }
        }
        __syncwarp();
    }

    {
        const int b = myrow >> 10;
        const int a = myrow & 1023;
        const float* vb = vel + (size_t)b * (1024 * 3);
        const int i1 = (int)(unsigned)k1;
        const int i2 = (int)(unsigned)k2;
        const int i3 = (int)(unsigned)k3;
        float sx = vb[a * 3 + 0], sy = vb[a * 3 + 1], sz = vb[a * 3 + 2];
        float nx = vb[i1 * 3 + 0] + vb[i2 * 3 + 0] + vb[i3 * 3 + 0];
        float ny = vb[i1 * 3 + 1] + vb[i2 * 3 + 1] + vb[i3 * 3 + 1];
        float nz = vb[i1 * 3 + 2] + vb[i2 * 3 + 2] + vb[i3 * 3 + 2];
        const float third = 1.0f / 3.0f;
        float* c = g_comb + (size_t)myrow * 6;
        c[0] = sx; c[1] = sy; c[2] = sz;
        c[3] = sx - nx * third;
        c[4] = sy - ny * third;
        c[5] = sz - nz * third;
    }
}

// ---------------------------------------------------------------------------
// Kernel 2: fused MLP. GEMM1+ReLU+LN in fp32, then GEMM2 on tensor cores via
// mma.sync m16n8k16 fp16 with hi/lo split (3 MMAs, fp32 accumulate).
// Block = 128 rows, 8 warps (warp w -> rows 16w..16w+15). N in 2 halves of
// 128 (64 fp32 acc regs), K in 4 chunks of 64 staged through smem.
// ---------------------------------------------------------------------------

#define AS_U32 132                 // A smem row stride in u32 (conflict-free)
#define A_BYTES (128 * AS_U32 * 4) // 67584 per matrix

#define OFF_W1   0                 // 6144
#define OFF_B1   6144              // 1024
#define OFF_G    7168              // 1024
#define OFF_BT   8192              // 1024
#define OFF_B2   9216              // 1024
#define OFF_CMB  10240             // 3072
#define OFF_AHI  13312             // 67584
#define OFF_ALO  (OFF_AHI + A_BYTES)            // 80896
#define OFF_BH   (OFF_ALO + A_BYTES)            // 148480, 16384
#define OFF_BL   (OFF_BH + 16384)               // 164864, 16384
#define SMEM_MLP (OFF_BL + 16384)               // 181248

__device__ __forceinline__ void mma_hff(float d[4], const uint32_t a[4],
                                        uint32_t b0, uint32_t b1) {
    asm volatile(
        "mma.sync.aligned.m16n8k16.row.col.f32.f16.f16.f32 "
        "{%0,%1,%2,%3}, {%4,%5,%6,%7}, {%8,%9}, {%0,%1,%2,%3};"
        : "+f"(d[0]), "+f"(d[1]), "+f"(d[2]), "+f"(d[3])
        : "r"(a[0]), "r"(a[1]), "r"(a[2]), "r"(a[3]), "r"(b0), "r"(b1));
}

__global__ void __launch_bounds__(256) mlp_kernel(
    const float* __restrict__ W1, const float* __restrict__ b1,
    const float* __restrict__ gamma, const float* __restrict__ beta,
    const float* __restrict__ b2, float* __restrict__ out)
{
    extern __shared__ char smc[];
    float* smf = (float*)smc;

    const int t = threadIdx.x;
    const int wid = t >> 5;
    const int lane = t & 31;
    const int row0 = blockIdx.x * 128;

    for (int i = t; i < 6 * 256; i += 256) smf[OFF_W1 / 4 + i] = W1[i];
    smf[OFF_B1 / 4 + t] = b1[t];
    smf[OFF_G  / 4 + t] = gamma[t];
    smf[OFF_BT / 4 + t] = beta[t];
    smf[OFF_B2 / 4 + t] = b2[t];
    for (int i = t; i < 128 * 6; i += 256)
        smf[OFF_CMB / 4 + i] = g_comb[(size_t)row0 * 6 + i];
    __syncthreads();

    // ---- Phase A: GEMM1 + relu (pass 1: stats; pass 2: LN -> fp16 hi/lo)
    {
        const int r = t >> 1;     // row 0..127
        const int q = t & 1;      // e-half
        const float* cm = smf + OFF_CMB / 4 + r * 6;
        const float c0 = cm[0], c1 = cm[1], c2 = cm[2];
        const float c3 = cm[3], c4 = cm[4], c5 = cm[5];
        const float2* w1v = (const float2*)(smc + OFF_W1);
        const float2* b1v = (const float2*)(smc + OFF_B1);

        float sum = 0.f, sq = 0.f;
        #pragma unroll 8
        for (int pe = 0; pe < 64; pe++) {
            const int pidx = 64 * q + pe;
            float2 bp = b1v[pidx];
            float x0 = bp.x, x1 = bp.y;
            float2 w;
            w = w1v[0 * 128 + pidx]; x0 = fmaf(c0, w.x, x0); x1 = fmaf(c0, w.y, x1);
            w = w1v[1 * 128 + pidx]; x0 = fmaf(c1, w.x, x0); x1 = fmaf(c1, w.y, x1);
            w = w1v[2 * 128 + pidx]; x0 = fmaf(c2, w.x, x0); x1 = fmaf(c2, w.y, x1);
            w = w1v[3 * 128 + pidx]; x0 = fmaf(c3, w.x, x0); x1 = fmaf(c3, w.y, x1);
            w = w1v[4 * 128 + pidx]; x0 = fmaf(c4, w.x, x0); x1 = fmaf(c4, w.y, x1);
            w = w1v[5 * 128 + pidx]; x0 = fmaf(c5, w.x, x0); x1 = fmaf(c5, w.y, x1);
            x0 = fmaxf(x0, 0.f);
            x1 = fmaxf(x1, 0.f);
            sum += x0 + x1;
            sq = fmaf(x0, x0, fmaf(x1, x1, sq));
        }
        sum += __shfl_xor_sync(FULLMASK, sum, 1);
        sq  += __shfl_xor_sync(FULLMASK, sq, 1);
        const float mu   = sum * (1.f / 256.f);
        const float var  = sq * (1.f / 256.f) - mu * mu;
        const float rstd = rsqrtf(var + 1e-5f);

        const float2* gv2 = (const float2*)(smc + OFF_G);
        const float2* bt2 = (const float2*)(smc + OFF_BT);
        uint32_t* ahi = (uint32_t*)(smc + OFF_AHI) + r * AS_U32 + 64 * q;
        uint32_t* alo = (uint32_t*)(smc + OFF_ALO) + r * AS_U32 + 64 * q;
        #pragma unroll 8
        for (int pe = 0; pe < 64; pe++) {
            const int pidx = 64 * q + pe;
            float2 bp = b1v[pidx];
            float x0 = bp.x, x1 = bp.y;
            float2 w;
            w = w1v[0 * 128 + pidx]; x0 = fmaf(c0, w.x, x0); x1 = fmaf(c0, w.y, x1);
            w = w1v[1 * 128 + pidx]; x0 = fmaf(c1, w.x, x0); x1 = fmaf(c1, w.y, x1);
            w = w1v[2 * 128 + pidx]; x0 = fmaf(c2, w.x, x0); x1 = fmaf(c2, w.y, x1);
            w = w1v[3 * 128 + pidx]; x0 = fmaf(c3, w.x, x0); x1 = fmaf(c3, w.y, x1);
            w = w1v[4 * 128 + pidx]; x0 = fmaf(c4, w.x, x0); x1 = fmaf(c4, w.y, x1);
            w = w1v[5 * 128 + pidx]; x0 = fmaf(c5, w.x, x0); x1 = fmaf(c5, w.y, x1);
            x0 = fmaxf(x0, 0.f);
            x1 = fmaxf(x1, 0.f);
            float2 gp = gv2[pidx];
            float2 tp = bt2[pidx];
            float y0 = fmaf((x0 - mu) * rstd, gp.x, tp.x);
            float y1 = fmaf((x1 - mu) * rstd, gp.y, tp.y);
            float h0, l0, h1, l1;
            splitf(y0, h0, l0);
            splitf(y1, h1, l1);
            ahi[pe] = pkh2(h0, h1);
            alo[pe] = pkh2(l0, l1);
        }
    }
    __syncthreads();

    // ---- Phase B: out = h @ W2 + b2 on tensor cores (3-MMA fp16 split)
    const uint32_t* Ahi = (const uint32_t*)(smc + OFF_AHI) + wid * 16 * AS_U32;
    const uint32_t* Alo = (const uint32_t*)(smc + OFF_ALO) + wid * 16 * AS_U32;
    const int arow = (lane >> 2);            // 0..7
    const int acol = (lane & 3);             // u32 col within k-step

    #pragma unroll 1
    for (int nh = 0; nh < 2; nh++) {
        float acc[16][4];
        #pragma unroll
        for (int nf = 0; nf < 16; nf++)
            #pragma unroll
            for (int j = 0; j < 4; j++) acc[nf][j] = 0.f;

        #pragma unroll 1
        for (int c = 0; c < 4; c++) {
            __syncthreads();   // previous chunk fully consumed
            {
                const float4* sh = (const float4*)(g_bhi + (size_t)(nh * 4 + c) * 16384);
                const float4* sl = (const float4*)(g_blo + (size_t)(nh * 4 + c) * 16384);
                float4* dh = (float4*)(smc + OFF_BH);
                float4* dl = (float4*)(smc + OFF_BL);
                #pragma unroll
                for (int i = 0; i < 4; i++) {
                    dh[t + 256 * i] = sh[t + 256 * i];
                    dl[t + 256 * i] = sl[t + 256 * i];
                }
            }
            __syncthreads();

            #pragma unroll
            for (int kkc = 0; kkc < 4; kkc++) {
                const int ks = c * 4 + kkc;            // global k-step
                const int kb = ks * 8 + acol;          // u32 col base
                uint32_t ah[4], al[4];
                ah[0] = Ahi[(arow + 0) * AS_U32 + kb + 0];
                ah[1] = Ahi[(arow + 8) * AS_U32 + kb + 0];
                ah[2] = Ahi[(arow + 0) * AS_U32 + kb + 4];
                ah[3] = Ahi[(arow + 8) * AS_U32 + kb + 4];
                al[0] = Alo[(arow + 0) * AS_U32 + kb + 0];
                al[1] = Alo[(arow + 8) * AS_U32 + kb + 0];
                al[2] = Alo[(arow + 0) * AS_U32 + kb + 4];
                al[3] = Alo[(arow + 8) * AS_U32 + kb + 4];
                #pragma unroll
                for (int nf = 0; nf < 16; nf++) {
                    const int boff = ((kkc * 16 + nf) * 32 + lane) * 8;
                    uint2 bh = *(const uint2*)(smc + OFF_BH + boff);
                    uint2 bl = *(const uint2*)(smc + OFF_BL + boff);
                    mma_hff(acc[nf], ah, bh.x, bh.y);
                    mma_hff(acc[nf], ah, bl.x, bl.y);
                    mma_hff(acc[nf], al, bh.x, bh.y);
                }
            }
        }

        // epilogue for this n-half
        const int gr = row0 + wid * 16 + arow;
        float* o0 = out + (size_t)gr * 256;
        float* o1 = o0 + 8 * 256;
        const float* b2s = smf + OFF_B2 / 4;
        #pragma unroll
        for (int nf = 0; nf < 16; nf++) {
            const int col = nh * 128 + nf * 8 + (lane & 3) * 2;
            float bx = b2s[col], by = b2s[col + 1];
            float2 v0 = make_float2(acc[nf][0] + bx, acc[nf][1] + by);
            float2 v1 = make_float2(acc[nf][2] + bx, acc[nf][3] + by);
            *(float2*)(o0 + col) = v0;
            *(float2*)(o1 + col) = v1;
        }
    }
}

// ---------------------------------------------------------------------------

extern "C" void kernel_launch(void* const* d_in, const int* in_sizes, int n_in,
                              void* d_out, int out_size) {
    const float* vel   = (const float*)d_in[0];
    const float* dm    = (const float*)d_in[1];
    const float* W1    = (const float*)d_in[2];
    const float* b1    = (const float*)d_in[3];
    const float* gamma = (const float*)d_in[4];
    const float* beta  = (const float*)d_in[5];
    const float* W2    = (const float*)d_in[6];
    const float* b2    = (const float*)d_in[7];
    float* out = (float*)d_out;

    w2prep_kernel<<<64, 256>>>(W2);
    topk_kernel<<<65536 / (32 * TK_WARPS), TK_WARPS * 32>>>(dm, vel);

    cudaFuncSetAttribute(mlp_kernel, cudaFuncAttributeMaxDynamicSharedMemorySize,
                         SMEM_MLP);
    mlp_kernel<<<512, 256, SMEM_MLP>>>(W1, b1, gamma, beta, b2, out);
}